// round 1
// baseline (speedup 1.0000x reference)
#include <cuda_runtime.h>
#include <cuda_bf16.h>

#define Bn 8192
#define En 16
#define Zn 256
#define Hn 1024
#define Un 256

#define TILE_M 64
#define MAX_TILES (Bn / TILE_M + En)   // 144 upper bound
#define NTHREADS 256
#define LDA 260                         // padded row stride (floats), mult of 4

// smem: As[64][260] + Aout[64][260] + Ws[16][68]
#define SMEM_FLOATS (2 * TILE_M * LDA + 16 * 68)
#define SMEM_BYTES (SMEM_FLOATS * 4)

// -------- device scratch (no allocations allowed) --------
__device__ int g_cnt[En];
__device__ int g_off[En];
__device__ int g_cur[En];
__device__ int g_perm[Bn];
__device__ int g_tile_e[MAX_TILES];
__device__ int g_tile_start[MAX_TILES];
__device__ int g_tile_rows[MAX_TILES];
__device__ int g_ntiles;

// -------- setup kernels --------
__global__ void k_zero() {
    int t = threadIdx.x;
    if (t < En) { g_cnt[t] = 0; g_cur[t] = 0; }
}

__global__ void k_hist(const int* __restrict__ rng) {
    __shared__ int s[En];
    if (threadIdx.x < En) s[threadIdx.x] = 0;
    __syncthreads();
    int i = blockIdx.x * blockDim.x + threadIdx.x;
    if (i < Bn) atomicAdd(&s[rng[i]], 1);
    __syncthreads();
    if (threadIdx.x < En) atomicAdd(&g_cnt[threadIdx.x], s[threadIdx.x]);
}

__global__ void k_scan() {
    if (threadIdx.x == 0 && blockIdx.x == 0) {
        int acc = 0, nt = 0;
        for (int e = 0; e < En; e++) {
            g_off[e] = acc;
            int c = g_cnt[e];
            for (int s = 0; s < c; s += TILE_M) {
                g_tile_e[nt] = e;
                g_tile_start[nt] = acc + s;
                g_tile_rows[nt] = (c - s) < TILE_M ? (c - s) : TILE_M;
                nt++;
            }
            acc += c;
        }
        g_ntiles = nt;
    }
}

__global__ void k_scatter(const int* __restrict__ rng) {
    int i = blockIdx.x * blockDim.x + threadIdx.x;
    if (i < Bn) {
        int e = rng[i];
        int p = atomicAdd(&g_cur[e], 1);
        g_perm[g_off[e] + p] = i;
    }
}

// -------- fused grouped GEMM --------
// Computes, for one 64-row tile of one expert:
//   a = z_tile @ Wz[e]^T + bz[e]           (64 x 256)  -> smem
//   h = relu(a @ Wh[e]^T + bh[e])          (64 x 1024) -> out
//   v = u_tile @ Wu[e]^T                   (64 x 256)  -> out
//
// C[m][n] = sum_k A[m][k] * W[n][k], K = 256, one 64-wide N chunk per call.
__device__ __forceinline__ void gemm_chunk(
    const float* __restrict__ Asm,   // smem A, [64][LDA]
    const float* __restrict__ Wg,    // expert weight base, row-major [N][256]
    float* __restrict__ Ws,          // smem W staging [16][68]
    int n0, float acc[4][4], int tx, int ty, int tid)
{
#pragma unroll
    for (int i = 0; i < 4; i++)
#pragma unroll
        for (int j = 0; j < 4; j++) acc[i][j] = 0.0f;

    for (int kt = 0; kt < 256; kt += 16) {
        // stage W[n0+n][kt..kt+15] -> Ws[kk][n], transposed
        {
            int n  = tid >> 2;            // 0..63
            int k4 = (tid & 3) * 4;       // 0,4,8,12
            const float4 w4 = *(const float4*)(Wg + (size_t)(n0 + n) * 256 + kt + k4);
            Ws[(k4 + 0) * 68 + n] = w4.x;
            Ws[(k4 + 1) * 68 + n] = w4.y;
            Ws[(k4 + 2) * 68 + n] = w4.z;
            Ws[(k4 + 3) * 68 + n] = w4.w;
        }
        __syncthreads();
#pragma unroll
        for (int kk = 0; kk < 16; kk++) {
            float af[4];
            float4 wf = *(const float4*)(Ws + kk * 68 + tx * 4);
#pragma unroll
            for (int i = 0; i < 4; i++) af[i] = Asm[(ty * 4 + i) * LDA + kt + kk];
#pragma unroll
            for (int i = 0; i < 4; i++) {
                acc[i][0] += af[i] * wf.x;
                acc[i][1] += af[i] * wf.y;
                acc[i][2] += af[i] * wf.z;
                acc[i][3] += af[i] * wf.w;
            }
        }
        __syncthreads();
    }
}

__global__ __launch_bounds__(NTHREADS) void k_moe(
    const float* __restrict__ z, const float* __restrict__ u,
    const float* __restrict__ Wz, const float* __restrict__ bz,
    const float* __restrict__ Wh, const float* __restrict__ bh,
    const float* __restrict__ Wu, float* __restrict__ out)
{
    int t = blockIdx.x;
    if (t >= g_ntiles) return;
    const int e     = g_tile_e[t];
    const int start = g_tile_start[t];
    const int rows  = g_tile_rows[t];

    extern __shared__ float sm[];
    float* As   = sm;                       // [64][LDA]
    float* Aout = sm + TILE_M * LDA;        // [64][LDA]
    float* Ws   = sm + 2 * TILE_M * LDA;    // [16][68]

    __shared__ int s_samp[TILE_M];

    const int tid = threadIdx.x;
    const int tx = tid & 15;   // N dim
    const int ty = tid >> 4;   // M dim

    if (tid < TILE_M) s_samp[tid] = (tid < rows) ? g_perm[start + tid] : -1;
    __syncthreads();

    // ---- load z tile ----
    for (int idx = tid; idx < TILE_M * 64; idx += NTHREADS) {
        int m = idx >> 6, c4 = idx & 63;
        float4 v4 = make_float4(0.f, 0.f, 0.f, 0.f);
        int s = s_samp[m];
        if (s >= 0) v4 = *(const float4*)(z + (size_t)s * Zn + c4 * 4);
        *(float4*)(As + m * LDA + c4 * 4) = v4;
    }
    __syncthreads();

    // ---- phase 1: a = z @ Wz^T + bz  -> Aout (smem) ----
    const float* Wze = Wz + (size_t)e * Zn * Zn;
    const float* bze = bz + (size_t)e * Zn;
    for (int nc = 0; nc < Zn / 64; nc++) {
        float acc[4][4];
        gemm_chunk(As, Wze, Ws, nc * 64, acc, tx, ty, tid);
#pragma unroll
        for (int i = 0; i < 4; i++) {
            int m = ty * 4 + i;
#pragma unroll
            for (int j = 0; j < 4; j++) {
                int n = nc * 64 + tx * 4 + j;
                Aout[m * LDA + n] = acc[i][j] + bze[n];
            }
        }
    }
    __syncthreads();

    // ---- phase 2: h = relu(a @ Wh^T + bh) -> out[0 .. B*H) ----
    const float* Whe = Wh + (size_t)e * Hn * Zn;
    const float* bhe = bh + (size_t)e * Hn;
    for (int nc = 0; nc < Hn / 64; nc++) {
        float acc[4][4];
        gemm_chunk(Aout, Whe, Ws, nc * 64, acc, tx, ty, tid);
#pragma unroll
        for (int i = 0; i < 4; i++) {
            int m = ty * 4 + i;
            int s = s_samp[m];
            if (s >= 0) {
                int n = nc * 64 + tx * 4;
                float4 o;
                o.x = fmaxf(acc[i][0] + bhe[n + 0], 0.f);
                o.y = fmaxf(acc[i][1] + bhe[n + 1], 0.f);
                o.z = fmaxf(acc[i][2] + bhe[n + 2], 0.f);
                o.w = fmaxf(acc[i][3] + bhe[n + 3], 0.f);
                *(float4*)(out + (size_t)s * Hn + n) = o;
            }
        }
    }

    // ---- load u tile (As is free; syncs in phase 2 ordered all prior reads) ----
    for (int idx = tid; idx < TILE_M * 64; idx += NTHREADS) {
        int m = idx >> 6, c4 = idx & 63;
        float4 v4 = make_float4(0.f, 0.f, 0.f, 0.f);
        int s = s_samp[m];
        if (s >= 0) v4 = *(const float4*)(u + (size_t)s * Un + c4 * 4);
        *(float4*)(As + m * LDA + c4 * 4) = v4;
    }
    __syncthreads();

    // ---- phase 3: v = u @ Wu^T -> out[B*H ...) ----
    const float* Wue = Wu + (size_t)e * Un * Un;
    float* outv = out + (size_t)Bn * Hn;
    for (int nc = 0; nc < Un / 64; nc++) {
        float acc[4][4];
        gemm_chunk(As, Wue, Ws, nc * 64, acc, tx, ty, tid);
#pragma unroll
        for (int i = 0; i < 4; i++) {
            int m = ty * 4 + i;
            int s = s_samp[m];
            if (s >= 0) {
                int n = nc * 64 + tx * 4;
                float4 o;
                o.x = acc[i][0]; o.y = acc[i][1]; o.z = acc[i][2]; o.w = acc[i][3];
                *(float4*)(outv + (size_t)s * Un + n) = o;
            }
        }
    }
}

extern "C" void kernel_launch(void* const* d_in, const int* in_sizes, int n_in,
                              void* d_out, int out_size) {
    (void)in_sizes; (void)n_in; (void)out_size;
    const float* z  = (const float*)d_in[0];
    const float* u  = (const float*)d_in[1];
    const int*   rng = (const int*)d_in[2];
    const float* Wz = (const float*)d_in[3];
    const float* bz = (const float*)d_in[4];
    const float* Wh = (const float*)d_in[5];
    const float* bh = (const float*)d_in[6];
    const float* Wu = (const float*)d_in[7];
    float* out = (float*)d_out;

    cudaFuncSetAttribute(k_moe, cudaFuncAttributeMaxDynamicSharedMemorySize, SMEM_BYTES);

    k_zero<<<1, 32>>>();
    k_hist<<<Bn / 256, 256>>>(rng);
    k_scan<<<1, 32>>>();
    k_scatter<<<Bn / 256, 256>>>(rng);
    k_moe<<<MAX_TILES, NTHREADS, SMEM_BYTES>>>(z, u, Wz, bz, Wh, bh, Wu, out);
}

// round 3
// speedup vs baseline: 2.8354x; 2.8354x over previous
#include <cuda_runtime.h>
#include <cuda_bf16.h>
#include <cstdint>

#define Bn 8192
#define En 16
#define Zn 256
#define Hn 1024
#define Un 256
#define TM 64
#define MAXT (Bn/TM + En)      // 144
#define NT 256
#define NC 128                 // N chunk
#define KC 64                  // K chunk
#define LDA 264                // A smem row stride (elems)
#define LDB 72                 // B smem row stride (elems)
#define BPART (128*LDB*2)      // bytes per B smem part (18432)

// smem byte offsets
#define OASH 0
#define OASL (TM*LDA*2)
#define OA2H (2*TM*LDA*2)
#define OA2L (3*TM*LDA*2)
#define OBS  (4*TM*LDA*2)
#define SMEM_DYN (OBS + 4*BPART)   // 135168 + 73728 = 208896

// ---------------- device scratch ----------------
__device__ int g_cnt[En], g_off[En], g_cur[En];
__device__ int g_perm[Bn];
__device__ int g_te[MAXT], g_ts[MAXT], g_tr[MAXT];
__device__ int g_ntiles;

__device__ __nv_bfloat16 g_Wzh[(size_t)En*Zn*Zn], g_Wzl[(size_t)En*Zn*Zn];
__device__ __nv_bfloat16 g_Whh[(size_t)En*Hn*Zn], g_Whl[(size_t)En*Hn*Zn];
__device__ __nv_bfloat16 g_Wuh[(size_t)En*Un*Un], g_Wul[(size_t)En*Un*Un];
__device__ __nv_bfloat16 g_zh[(size_t)Bn*Zn],     g_zl[(size_t)Bn*Zn];
__device__ __nv_bfloat16 g_uh[(size_t)Bn*Un],     g_ul[(size_t)Bn*Un];

// ---------------- helpers ----------------
__device__ __forceinline__ uint32_t s2u(const void* p) {
    uint32_t a;
    asm("{ .reg .u64 t; cvta.to.shared.u64 t, %1; cvt.u32.u64 %0, t; }" : "=r"(a) : "l"(p));
    return a;
}
__device__ __forceinline__ void cpa16(uint32_t dst, const void* src, uint32_t sz) {
    asm volatile("cp.async.ca.shared.global [%0], [%1], 16, %2;"
                 :: "r"(dst), "l"(src), "r"(sz));
}
__device__ __forceinline__ void cpa_commit() { asm volatile("cp.async.commit_group;" ::: "memory"); }
template<int N> __device__ __forceinline__ void cpa_wait() {
    asm volatile("cp.async.wait_group %0;" :: "n"(N) : "memory");
}
__device__ __forceinline__ void ldm4(uint32_t r[4], uint32_t addr) {
    asm volatile("ldmatrix.sync.aligned.m8n8.x4.shared.b16 {%0,%1,%2,%3}, [%4];"
                 : "=r"(r[0]), "=r"(r[1]), "=r"(r[2]), "=r"(r[3]) : "r"(addr));
}
__device__ __forceinline__ void mma16816(float c[4], const uint32_t a[4], uint32_t b0, uint32_t b1) {
    asm volatile("mma.sync.aligned.m16n8k16.row.col.f32.bf16.bf16.f32 "
                 "{%0,%1,%2,%3}, {%4,%5,%6,%7}, {%8,%9}, {%0,%1,%2,%3};"
                 : "+f"(c[0]), "+f"(c[1]), "+f"(c[2]), "+f"(c[3])
                 : "r"(a[0]), "r"(a[1]), "r"(a[2]), "r"(a[3]), "r"(b0), "r"(b1));
}
__device__ __forceinline__ void bsplit(float x, __nv_bfloat16& h, __nv_bfloat16& l) {
    h = __float2bfloat16_rn(x);
    l = __float2bfloat16_rn(x - __bfloat162float(h));
}

// ---------------- setup kernels ----------------
__global__ void k_zero() {
    int t = threadIdx.x;
    if (t < En) { g_cnt[t] = 0; g_cur[t] = 0; }
}
__global__ void k_hist(const int* __restrict__ rng) {
    __shared__ int s[En];
    if (threadIdx.x < En) s[threadIdx.x] = 0;
    __syncthreads();
    int i = blockIdx.x * blockDim.x + threadIdx.x;
    if (i < Bn) atomicAdd(&s[rng[i]], 1);
    __syncthreads();
    if (threadIdx.x < En) atomicAdd(&g_cnt[threadIdx.x], s[threadIdx.x]);
}
__global__ void k_scan() {
    if (threadIdx.x == 0 && blockIdx.x == 0) {
        int acc = 0, nt = 0;
        for (int e = 0; e < En; e++) {
            g_off[e] = acc;
            int c = g_cnt[e];
            for (int s = 0; s < c; s += TM) {
                g_te[nt] = e;
                g_ts[nt] = acc + s;
                g_tr[nt] = (c - s) < TM ? (c - s) : TM;
                nt++;
            }
            acc += c;
        }
        g_ntiles = nt;
    }
}
__global__ void k_scatter(const int* __restrict__ rng) {
    int i = blockIdx.x * blockDim.x + threadIdx.x;
    if (i < Bn) {
        int e = rng[i];
        int p = atomicAdd(&g_cur[e], 1);
        g_perm[g_off[e] + p] = i;
    }
}

// convert fp32 -> bf16 hi/lo (4 floats per thread)
__global__ void k_cvt(const float* __restrict__ s, int which, int n4) {
    int i = blockIdx.x * blockDim.x + threadIdx.x;
    if (i >= n4) return;
    __nv_bfloat16 *dh, *dl;
    if (which == 0)      { dh = g_Wzh; dl = g_Wzl; }
    else if (which == 1) { dh = g_Whh; dl = g_Whl; }
    else if (which == 2) { dh = g_Wuh; dl = g_Wul; }
    else if (which == 3) { dh = g_zh;  dl = g_zl;  }
    else                 { dh = g_uh;  dl = g_ul;  }
    float4 v = __ldg((const float4*)s + i);
    __nv_bfloat16 h0,h1,h2,h3,l0,l1,l2,l3;
    bsplit(v.x,h0,l0); bsplit(v.y,h1,l1); bsplit(v.z,h2,l2); bsplit(v.w,h3,l3);
    union { __nv_bfloat162 b[2]; uint2 q; } H, L;
    H.b[0] = __halves2bfloat162(h0,h1); H.b[1] = __halves2bfloat162(h2,h3);
    L.b[0] = __halves2bfloat162(l0,l1); L.b[1] = __halves2bfloat162(l2,l3);
    ((uint2*)dh)[i] = H.q;
    ((uint2*)dl)[i] = L.q;
}

// ---------------- staging ----------------
// A tile: 64 rows x 256 bf16 (hi+lo), gathered rows, zero-fill invalid
__device__ __forceinline__ void stage_a(uint32_t ah, uint32_t al,
                                        const __nv_bfloat16* gh, const __nv_bfloat16* gl,
                                        const int* ss, int tid) {
    for (int i = tid; i < TM * 32; i += NT) {
        int r = i >> 5, c = (i & 31) << 3;          // 8 elems = 16B
        int s = ss[r];
        uint32_t sz = (s >= 0) ? 16u : 0u;
        size_t g = (size_t)(s >= 0 ? s : 0) * 256 + c;
        uint32_t o = (uint32_t)(r * LDA + c) * 2;
        cpa16(ah + o, gh + g, sz);
        cpa16(al + o, gl + g, sz);
    }
}
// B chunk: 128 rows x 64 bf16 (hi+lo)
__device__ __forceinline__ void stage_b(uint32_t bh, uint32_t bl,
                                        const __nv_bfloat16* gh, const __nv_bfloat16* gl,
                                        int kc, int tid) {
    for (int i = tid; i < 128 * 8; i += NT) {
        int r = i >> 3, c = (i & 7) << 3;
        size_t g = (size_t)r * 256 + kc * KC + c;
        uint32_t o = (uint32_t)(r * LDB + c) * 2;
        cpa16(bh + o, gh + g, 16u);
        cpa16(bl + o, gl + g, 16u);
    }
}

// ---------------- GEMM for one 64x128 output chunk ----------------
// A in smem (hi/lo, [64][LDA]); B global bf16 hi/lo rows [*][256] at nbase;
// accum c[2][4][4] per warp (warp tile 32x32; warps 2x4).
__device__ __forceinline__ void gemm_nc(uint32_t aH, uint32_t aL, uint32_t obs,
                                        const __nv_bfloat16* gBh, const __nv_bfloat16* gBl,
                                        float c[2][4][4], int tid) {
    const int lane = tid & 31, warp = tid >> 5;
    const int wm = warp >> 2, wn = warp & 3;
    const int lrow = (lane & 7) + ((lane >> 3) & 1) * 8;
    const int lk8  = (lane >> 4) * 8;

#pragma unroll
    for (int mt = 0; mt < 2; mt++)
#pragma unroll
        for (int nt = 0; nt < 4; nt++)
#pragma unroll
            for (int j = 0; j < 4; j++) c[mt][nt][j] = 0.f;

    stage_b(obs, obs + BPART, gBh, gBl, 0, tid);
    cpa_commit();

    for (int kc = 0; kc < 4; kc++) {
        if (kc < 3) {
            uint32_t b = (uint32_t)((kc + 1) & 1);
            stage_b(obs + b * 2 * BPART, obs + (b * 2 + 1) * BPART, gBh, gBl, kc + 1, tid);
            cpa_commit();
            cpa_wait<1>();
        } else {
            cpa_wait<0>();
        }
        __syncthreads();

        const uint32_t bH = obs + (uint32_t)((kc & 1) * 2) * BPART;
        const uint32_t bL = bH + BPART;
#pragma unroll
        for (int k16 = 0; k16 < 4; k16++) {
            const int ka = kc * KC + k16 * 16;
            uint32_t ah[2][4], al[2][4];
#pragma unroll
            for (int mt = 0; mt < 2; mt++) {
                uint32_t ao = (uint32_t)((wm * 32 + mt * 16 + lrow) * LDA + ka + lk8) * 2;
                ldm4(ah[mt], aH + ao);
                ldm4(al[mt], aL + ao);
            }
            uint32_t bhf[2][4], blf[2][4];
#pragma unroll
            for (int ng = 0; ng < 2; ng++) {
                uint32_t bo = (uint32_t)((wn * 32 + ng * 16 + lrow) * LDB + k16 * 16 + lk8) * 2;
                ldm4(bhf[ng], bH + bo);
                ldm4(blf[ng], bL + bo);
            }
#pragma unroll
            for (int mt = 0; mt < 2; mt++) {
#pragma unroll
                for (int nt = 0; nt < 4; nt++) {
                    const int ng = nt >> 1, sel = nt & 1;
                    mma16816(c[mt][nt], ah[mt], bhf[ng][sel], bhf[ng][sel + 2]); // hi*hi
                    mma16816(c[mt][nt], ah[mt], blf[ng][sel], blf[ng][sel + 2]); // hi*lo
                    mma16816(c[mt][nt], al[mt], bhf[ng][sel], bhf[ng][sel + 2]); // lo*hi
                }
            }
        }
        __syncthreads();
    }
}

// ---------------- fused MoE kernel ----------------
__global__ __launch_bounds__(NT, 1)
void k_moe(const float* __restrict__ bz, const float* __restrict__ bhb,
           float* __restrict__ out) {
    const int bt = blockIdx.x;
    if (bt >= g_ntiles) return;
    const int e = g_te[bt], start = g_ts[bt], rows = g_tr[bt];
    const int tid = threadIdx.x, lane = tid & 31, warp = tid >> 5;
    const int wm = warp >> 2, wn = warp & 3;
    const int t4 = lane >> 2, t2 = (lane & 3) * 2;

    extern __shared__ char smc[];
    const uint32_t sm0 = s2u(smc);
    const uint32_t aSH = sm0 + OASH, aSL = sm0 + OASL;
    const uint32_t a2H = sm0 + OA2H, a2L = sm0 + OA2L;
    const uint32_t obs = sm0 + OBS;

    __shared__ int ss[TM];
    if (tid < TM) ss[tid] = (tid < rows) ? g_perm[start + tid] : -1;
    __syncthreads();

    // stage z tile
    stage_a(aSH, aSL, g_zh, g_zl, ss, tid);
    cpa_commit();

    float c[2][4][4];

    // ---- GEMM1: a = z @ Wz^T + bz -> A2 smem (bf16 hi/lo) ----
    {
        const __nv_bfloat16* Bh = g_Wzh + (size_t)e * Zn * Zn;
        const __nv_bfloat16* Bl = g_Wzl + (size_t)e * Zn * Zn;
        for (int nc = 0; nc < Zn / NC; nc++) {
            gemm_nc(aSH, aSL, obs, Bh + (size_t)nc * NC * Zn, Bl + (size_t)nc * NC * Zn, c, tid);
            const float* bzp = bz + (size_t)e * Zn + nc * NC;
#pragma unroll
            for (int mt = 0; mt < 2; mt++) {
                const int r0 = wm * 32 + mt * 16 + t4;
#pragma unroll
                for (int nt = 0; nt < 4; nt++) {
                    const int col = wn * 32 + nt * 8 + t2;
                    const float2 bb = *(const float2*)(bzp + col);
                    __nv_bfloat16 h0,l0,h1,l1;
                    bsplit(c[mt][nt][0] + bb.x, h0, l0);
                    bsplit(c[mt][nt][1] + bb.y, h1, l1);
                    uint32_t o = (uint32_t)(r0 * LDA + nc * NC + col) * 2;
                    *(__nv_bfloat162*)(smc + OA2H + o) = __halves2bfloat162(h0, h1);
                    *(__nv_bfloat162*)(smc + OA2L + o) = __halves2bfloat162(l0, l1);
                    bsplit(c[mt][nt][2] + bb.x, h0, l0);
                    bsplit(c[mt][nt][3] + bb.y, h1, l1);
                    o = (uint32_t)((r0 + 8) * LDA + nc * NC + col) * 2;
                    *(__nv_bfloat162*)(smc + OA2H + o) = __halves2bfloat162(h0, h1);
                    *(__nv_bfloat162*)(smc + OA2L + o) = __halves2bfloat162(l0, l1);
                }
            }
        }
    }
    __syncthreads();

    // stage u tile into As (overwrite z; GEMM1 done)
    stage_a(aSH, aSL, g_uh, g_ul, ss, tid);
    cpa_commit();

    // ---- GEMM2: h = relu(a @ Wh^T + bh) -> out ----
    {
        const __nv_bfloat16* Bh = g_Whh + (size_t)e * Hn * Zn;
        const __nv_bfloat16* Bl = g_Whl + (size_t)e * Hn * Zn;
        for (int nc = 0; nc < Hn / NC; nc++) {
            gemm_nc(a2H, a2L, obs, Bh + (size_t)nc * NC * Zn, Bl + (size_t)nc * NC * Zn, c, tid);
            const float* bhp = bhb + (size_t)e * Hn + nc * NC;
#pragma unroll
            for (int mt = 0; mt < 2; mt++) {
                const int r0 = wm * 32 + mt * 16 + t4;
                const int s0 = ss[r0], s1 = ss[r0 + 8];
#pragma unroll
                for (int nt = 0; nt < 4; nt++) {
                    const int col = wn * 32 + nt * 8 + t2;
                    const float2 bb = *(const float2*)(bhp + col);
                    if (s0 >= 0) {
                        float2 o;
                        o.x = fmaxf(c[mt][nt][0] + bb.x, 0.f);
                        o.y = fmaxf(c[mt][nt][1] + bb.y, 0.f);
                        *(float2*)(out + (size_t)s0 * Hn + nc * NC + col) = o;
                    }
                    if (s1 >= 0) {
                        float2 o;
                        o.x = fmaxf(c[mt][nt][2] + bb.x, 0.f);
                        o.y = fmaxf(c[mt][nt][3] + bb.y, 0.f);
                        *(float2*)(out + (size_t)s1 * Hn + nc * NC + col) = o;
                    }
                }
            }
        }
    }

    // ---- GEMM3: v = u @ Wu^T -> out + Bn*Hn ----
    {
        const __nv_bfloat16* Bh = g_Wuh + (size_t)e * Un * Un;
        const __nv_bfloat16* Bl = g_Wul + (size_t)e * Un * Un;
        float* outv = out + (size_t)Bn * Hn;
        for (int nc = 0; nc < Un / NC; nc++) {
            gemm_nc(aSH, aSL, obs, Bh + (size_t)nc * NC * Zn, Bl + (size_t)nc * NC * Zn, c, tid);
#pragma unroll
            for (int mt = 0; mt < 2; mt++) {
                const int r0 = wm * 32 + mt * 16 + t4;
                const int s0 = ss[r0], s1 = ss[r0 + 8];
#pragma unroll
                for (int nt = 0; nt < 4; nt++) {
                    const int col = wn * 32 + nt * 8 + t2;
                    if (s0 >= 0) {
                        float2 o; o.x = c[mt][nt][0]; o.y = c[mt][nt][1];
                        *(float2*)(outv + (size_t)s0 * Un + nc * NC + col) = o;
                    }
                    if (s1 >= 0) {
                        float2 o; o.x = c[mt][nt][2]; o.y = c[mt][nt][3];
                        *(float2*)(outv + (size_t)s1 * Un + nc * NC + col) = o;
                    }
                }
            }
        }
    }
}

// ---------------- launcher ----------------
extern "C" void kernel_launch(void* const* d_in, const int* in_sizes, int n_in,
                              void* d_out, int out_size) {
    (void)in_sizes; (void)n_in; (void)out_size;
    const float* z   = (const float*)d_in[0];
    const float* u   = (const float*)d_in[1];
    const int*   rng = (const int*)d_in[2];
    const float* Wz  = (const float*)d_in[3];
    const float* bz  = (const float*)d_in[4];
    const float* Wh  = (const float*)d_in[5];
    const float* bh  = (const float*)d_in[6];
    const float* Wu  = (const float*)d_in[7];
    float* out = (float*)d_out;

    cudaFuncSetAttribute(k_moe, cudaFuncAttributeMaxDynamicSharedMemorySize, SMEM_DYN);

    k_zero<<<1, 32>>>();
    k_hist<<<Bn / 256, 256>>>(rng);
    k_scan<<<1, 32>>>();
    k_scatter<<<Bn / 256, 256>>>(rng);

    const int nWz = En * Zn * Zn / 4, nWh = En * Hn * Zn / 4, nWu = En * Un * Un / 4;
    const int nz = Bn * Zn / 4, nu = Bn * Un / 4;
    k_cvt<<<(nWz + 255) / 256, 256>>>(Wz, 0, nWz);
    k_cvt<<<(nWh + 255) / 256, 256>>>(Wh, 1, nWh);
    k_cvt<<<(nWu + 255) / 256, 256>>>(Wu, 2, nWu);
    k_cvt<<<(nz + 255) / 256, 256>>>(z, 3, nz);
    k_cvt<<<(nu + 255) / 256, 256>>>(u, 4, nu);

    k_moe<<<MAXT, NT, SMEM_DYN>>>(bz, bh, out);
}

// round 4
// speedup vs baseline: 4.1242x; 1.4545x over previous
#include <cuda_runtime.h>
#include <cuda_fp16.h>
#include <cstdint>

#define Bn 8192
#define En 16
#define Zn 256
#define Hn 1024
#define Un 256
#define TM 64
#define MAXT (Bn/TM + En)      // 144
#define NT 512
#define NC 128                 // N chunk
#define KC 64                  // K chunk
#define LDA 264                // A smem row stride (halves)
#define LDB 72                 // B smem row stride (halves)
#define BPART (128*LDB*2)      // 18432 B per B-part

// smem byte offsets
#define OASH 0
#define OASL (TM*LDA*2)
#define OA2H (2*TM*LDA*2)
#define OA2L (3*TM*LDA*2)
#define OBS  (4*TM*LDA*2)      // 135168
#define SMEM_DYN (OBS + 4*BPART)   // 208896

// ---------------- device scratch ----------------
__device__ int g_cnt[En], g_off[En], g_cur[En];
__device__ int g_perm[Bn];
__device__ int g_te[MAXT], g_ts[MAXT], g_tr[MAXT];
__device__ int g_ntiles;

__device__ __half g_Wzh[(size_t)En*Zn*Zn], g_Wzl[(size_t)En*Zn*Zn];
__device__ __half g_Whh[(size_t)En*Hn*Zn];
__device__ __half g_Wuh[(size_t)En*Un*Un];
__device__ __half g_zh[(size_t)Bn*Zn], g_zl[(size_t)Bn*Zn];
__device__ __half g_uh[(size_t)Bn*Un], g_ul[(size_t)Bn*Un];

// ---------------- helpers ----------------
__device__ __forceinline__ uint32_t s2u(const void* p) {
    uint32_t a;
    asm("{ .reg .u64 t; cvta.to.shared.u64 t, %1; cvt.u32.u64 %0, t; }" : "=r"(a) : "l"(p));
    return a;
}
__device__ __forceinline__ void cpa16(uint32_t dst, const void* src, uint32_t sz) {
    asm volatile("cp.async.ca.shared.global [%0], [%1], 16, %2;"
                 :: "r"(dst), "l"(src), "r"(sz));
}
__device__ __forceinline__ void cpa_commit() { asm volatile("cp.async.commit_group;" ::: "memory"); }
template<int N> __device__ __forceinline__ void cpa_wait() {
    asm volatile("cp.async.wait_group %0;" :: "n"(N) : "memory");
}
__device__ __forceinline__ void ldm4(uint32_t r[4], uint32_t addr) {
    asm volatile("ldmatrix.sync.aligned.m8n8.x4.shared.b16 {%0,%1,%2,%3}, [%4];"
                 : "=r"(r[0]), "=r"(r[1]), "=r"(r[2]), "=r"(r[3]) : "r"(addr));
}
__device__ __forceinline__ void mma16816(float c[4], const uint32_t a[4], uint32_t b0, uint32_t b1) {
    asm volatile("mma.sync.aligned.m16n8k16.row.col.f32.f16.f16.f32 "
                 "{%0,%1,%2,%3}, {%4,%5,%6,%7}, {%8,%9}, {%0,%1,%2,%3};"
                 : "+f"(c[0]), "+f"(c[1]), "+f"(c[2]), "+f"(c[3])
                 : "r"(a[0]), "r"(a[1]), "r"(a[2]), "r"(a[3]), "r"(b0), "r"(b1));
}
__device__ __forceinline__ void hsplit(float x, __half& h, __half& l) {
    h = __float2half_rn(x);
    l = __float2half_rn(x - __half2float(h));
}

// ---------------- setup kernels ----------------
__global__ void k_zero() {
    int t = threadIdx.x;
    if (t < En) { g_cnt[t] = 0; g_cur[t] = 0; }
}
__global__ void k_hist(const int* __restrict__ rng) {
    __shared__ int s[En];
    if (threadIdx.x < En) s[threadIdx.x] = 0;
    __syncthreads();
    int i = blockIdx.x * blockDim.x + threadIdx.x;
    if (i < Bn) atomicAdd(&s[rng[i]], 1);
    __syncthreads();
    if (threadIdx.x < En) atomicAdd(&g_cnt[threadIdx.x], s[threadIdx.x]);
}
__global__ void k_scan() {
    if (threadIdx.x == 0 && blockIdx.x == 0) {
        int acc = 0, nt = 0;
        for (int e = 0; e < En; e++) {
            g_off[e] = acc;
            int c = g_cnt[e];
            for (int s = 0; s < c; s += TM) {
                g_te[nt] = e;
                g_ts[nt] = acc + s;
                g_tr[nt] = (c - s) < TM ? (c - s) : TM;
                nt++;
            }
            acc += c;
        }
        g_ntiles = nt;
    }
}
__global__ void k_scatter(const int* __restrict__ rng) {
    int i = blockIdx.x * blockDim.x + threadIdx.x;
    if (i < Bn) {
        int e = rng[i];
        int p = atomicAdd(&g_cur[e], 1);
        g_perm[g_off[e] + p] = i;
    }
}

// single fused fp32 -> fp16 (hi[,lo]) converter; one float4 per thread
#define NWz (En*Zn*Zn/4)
#define NWh (En*Hn*Zn/4)
#define NWu (En*Un*Un/4)
#define Nz4 (Bn*Zn/4)
#define Nu4 (Bn*Un/4)
#define NCVT (NWz + NWh + NWu + Nz4 + Nu4)   // 2,621,440

__global__ void k_cvt_all(const float* __restrict__ z, const float* __restrict__ u,
                          const float* __restrict__ Wz, const float* __restrict__ Wh,
                          const float* __restrict__ Wu) {
    int i = blockIdx.x * blockDim.x + threadIdx.x;
    if (i >= NCVT) return;
    const float* src; __half* dh; __half* dl; int j = i;
    if (j < NWz)                     { src = Wz; dh = g_Wzh; dl = g_Wzl; }
    else if ((j -= NWz) < NWh)       { src = Wh; dh = g_Whh; dl = nullptr; }
    else if ((j -= NWh) < NWu)       { src = Wu; dh = g_Wuh; dl = nullptr; }
    else if ((j -= NWu) < Nz4)       { src = z;  dh = g_zh;  dl = g_zl; }
    else     { j -= Nz4;               src = u;  dh = g_uh;  dl = g_ul; }
    float4 v = __ldg((const float4*)src + j);
    __half h0,h1,h2,h3,l0,l1,l2,l3;
    hsplit(v.x,h0,l0); hsplit(v.y,h1,l1); hsplit(v.z,h2,l2); hsplit(v.w,h3,l3);
    union { __half2 b[2]; uint2 q; } H, L;
    H.b[0] = __halves2half2(h0,h1); H.b[1] = __halves2half2(h2,h3);
    ((uint2*)dh)[j] = H.q;
    if (dl) {
        L.b[0] = __halves2half2(l0,l1); L.b[1] = __halves2half2(l2,l3);
        ((uint2*)dl)[j] = L.q;
    }
}

// ---------------- staging ----------------
__device__ __forceinline__ void stage_a(uint32_t ah, uint32_t al,
                                        const __half* gh, const __half* gl,
                                        const int* ss, int tid) {
    for (int i = tid; i < TM * 32; i += NT) {
        int r = i >> 5, c = (i & 31) << 3;
        int s = ss[r];
        uint32_t sz = (s >= 0) ? 16u : 0u;
        size_t g = (size_t)(s >= 0 ? s : 0) * 256 + c;
        uint32_t o = (uint32_t)(r * LDA + c) * 2;
        cpa16(ah + o, gh + g, sz);
        cpa16(al + o, gl + g, sz);
    }
}
__device__ __forceinline__ void stage_b2(uint32_t bh, const __half* gh, int kc, int tid) {
    for (int i = tid; i < 128 * 8; i += NT) {
        int r = i >> 3, c = (i & 7) << 3;
        size_t g = (size_t)r * 256 + kc * KC + c;
        cpa16(bh + (uint32_t)(r * LDB + c) * 2, gh + g, 16u);
    }
}
__device__ __forceinline__ void stage_b3(uint32_t bh, uint32_t bl,
                                         const __half* gh, const __half* gl, int kc, int tid) {
    for (int i = tid; i < 128 * 8; i += NT) {
        int r = i >> 3, c = (i & 7) << 3;
        size_t g = (size_t)r * 256 + kc * KC + c;
        uint32_t o = (uint32_t)(r * LDB + c) * 2;
        cpa16(bh + o, gh + g, 16u);
        cpa16(bl + o, gl + g, 16u);
    }
}

// ---------------- GEMM for one 64x128 output chunk ----------------
// PROD=3: c += Ah.Bh + Ah.Bl + Al.Bh  (GEMM1, full accuracy)
// PROD=2: c += Ah.Bh + Al.Bh          (B hi only)
template<int PROD>
__device__ __forceinline__ void gemm_nc(uint32_t aH, uint32_t aL, uint32_t obs,
                                        const __half* gBh, const __half* gBl,
                                        float c[4][4], int tid) {
    const int lane = tid & 31, warp = tid >> 5;
    const int wm = warp >> 2, wn = warp & 3;
    const int lrow = (lane & 7) + ((lane >> 3) & 1) * 8;
    const int lk8  = (lane >> 4) * 8;

#pragma unroll
    for (int nt = 0; nt < 4; nt++)
#pragma unroll
        for (int j = 0; j < 4; j++) c[nt][j] = 0.f;

    if (PROD == 3) stage_b3(obs, obs + BPART, gBh, gBl, 0, tid);
    else           stage_b2(obs, gBh, 0, tid);
    cpa_commit();

    for (int kc = 0; kc < 4; kc++) {
        if (kc < 3) {
            if (PROD == 3) {
                uint32_t b = (uint32_t)((kc + 1) & 1);
                stage_b3(obs + b * 2 * BPART, obs + (b * 2 + 1) * BPART, gBh, gBl, kc + 1, tid);
            } else {
                uint32_t b = (uint32_t)((kc + 1) % 3);
                stage_b2(obs + b * BPART, gBh, kc + 1, tid);
            }
            cpa_commit();
            cpa_wait<1>();
        } else {
            cpa_wait<0>();
        }
        __syncthreads();

        const uint32_t bH = (PROD == 3) ? obs + (uint32_t)((kc & 1) * 2) * BPART
                                        : obs + (uint32_t)(kc % 3) * BPART;
        const uint32_t bL = bH + BPART;
#pragma unroll
        for (int k16 = 0; k16 < 4; k16++) {
            const int ka = kc * KC + k16 * 16;
            uint32_t ah[4], al[4];
            const uint32_t ao = (uint32_t)((wm * 16 + lrow) * LDA + ka + lk8) * 2;
            ldm4(ah, aH + ao);
            ldm4(al, aL + ao);
            uint32_t bhf[2][4], blf[2][4];
#pragma unroll
            for (int ng = 0; ng < 2; ng++) {
                const uint32_t bo = (uint32_t)((wn * 32 + ng * 16 + lrow) * LDB + k16 * 16 + lk8) * 2;
                ldm4(bhf[ng], bH + bo);
                if (PROD == 3) ldm4(blf[ng], bL + bo);
            }
#pragma unroll
            for (int nt = 0; nt < 4; nt++) {
                const int ng = nt >> 1, sel = nt & 1;
                mma16816(c[nt], ah, bhf[ng][sel], bhf[ng][sel + 2]);
                if (PROD == 3) mma16816(c[nt], ah, blf[ng][sel], blf[ng][sel + 2]);
                mma16816(c[nt], al, bhf[ng][sel], bhf[ng][sel + 2]);
            }
        }
        if (PROD == 3) __syncthreads();   // double-buffer reuse guard
    }
}

// ---------------- fused MoE kernel ----------------
__global__ __launch_bounds__(NT, 1)
void k_moe(const float* __restrict__ bz, const float* __restrict__ bhb,
           float* __restrict__ out) {
    const int bt = blockIdx.x;
    if (bt >= g_ntiles) return;
    const int e = g_te[bt], start = g_ts[bt], rows = g_tr[bt];
    const int tid = threadIdx.x, lane = tid & 31, warp = tid >> 5;
    const int wm = warp >> 2, wn = warp & 3;
    const int t4 = lane >> 2, t2 = (lane & 3) * 2;

    extern __shared__ char smc[];
    const uint32_t sm0 = s2u(smc);
    const uint32_t aSH = sm0 + OASH, aSL = sm0 + OASL;
    const uint32_t a2H = sm0 + OA2H, a2L = sm0 + OA2L;
    const uint32_t obs = sm0 + OBS;

    __shared__ int ss[TM];
    if (tid < TM) ss[tid] = (tid < rows) ? g_perm[start + tid] : -1;
    __syncthreads();

    stage_a(aSH, aSL, g_zh, g_zl, ss, tid);
    cpa_commit();

    float c[4][4];

    // ---- GEMM1: a = z @ Wz^T + bz -> A2 smem (fp16 hi/lo), 3-product ----
    {
        const __half* Bh = g_Wzh + (size_t)e * Zn * Zn;
        const __half* Bl = g_Wzl + (size_t)e * Zn * Zn;
        for (int nc = 0; nc < Zn / NC; nc++) {
            gemm_nc<3>(aSH, aSL, obs, Bh + (size_t)nc * NC * Zn, Bl + (size_t)nc * NC * Zn, c, tid);
            const float* bzp = bz + (size_t)e * Zn + nc * NC;
            const int r0 = wm * 16 + t4;
#pragma unroll
            for (int nt = 0; nt < 4; nt++) {
                const int col = wn * 32 + nt * 8 + t2;
                const float2 bb = *(const float2*)(bzp + col);
                __half h0,l0,h1,l1;
                hsplit(c[nt][0] + bb.x, h0, l0);
                hsplit(c[nt][1] + bb.y, h1, l1);
                uint32_t o = (uint32_t)(r0 * LDA + nc * NC + col) * 2;
                *(__half2*)(smc + OA2H + o) = __halves2half2(h0, h1);
                *(__half2*)(smc + OA2L + o) = __halves2half2(l0, l1);
                hsplit(c[nt][2] + bb.x, h0, l0);
                hsplit(c[nt][3] + bb.y, h1, l1);
                o = (uint32_t)((r0 + 8) * LDA + nc * NC + col) * 2;
                *(__half2*)(smc + OA2H + o) = __halves2half2(h0, h1);
                *(__half2*)(smc + OA2L + o) = __halves2half2(l0, l1);
            }
        }
    }
    __syncthreads();

    // stage u tile into As (GEMM1 fully done with As)
    stage_a(aSH, aSL, g_uh, g_ul, ss, tid);
    cpa_commit();

    // ---- GEMM2: h = relu(a @ Wh^T + bh) -> out, 2-product ----
    {
        const __half* Bh = g_Whh + (size_t)e * Hn * Zn;
        for (int nc = 0; nc < Hn / NC; nc++) {
            gemm_nc<2>(a2H, a2L, obs, Bh + (size_t)nc * NC * Zn, nullptr, c, tid);
            const float* bhp = bhb + (size_t)e * Hn + nc * NC;
            const int r0 = wm * 16 + t4;
            const int s0 = ss[r0], s1 = ss[r0 + 8];
#pragma unroll
            for (int nt = 0; nt < 4; nt++) {
                const int col = wn * 32 + nt * 8 + t2;
                const float2 bb = *(const float2*)(bhp + col);
                if (s0 >= 0) {
                    float2 o;
                    o.x = fmaxf(c[nt][0] + bb.x, 0.f);
                    o.y = fmaxf(c[nt][1] + bb.y, 0.f);
                    *(float2*)(out + (size_t)s0 * Hn + nc * NC + col) = o;
                }
                if (s1 >= 0) {
                    float2 o;
                    o.x = fmaxf(c[nt][2] + bb.x, 0.f);
                    o.y = fmaxf(c[nt][3] + bb.y, 0.f);
                    *(float2*)(out + (size_t)s1 * Hn + nc * NC + col) = o;
                }
            }
        }
    }

    // ---- GEMM3: v = u @ Wu^T -> out + Bn*Hn, 2-product ----
    {
        const __half* Bh = g_Wuh + (size_t)e * Un * Un;
        float* outv = out + (size_t)Bn * Hn;
        for (int nc = 0; nc < Un / NC; nc++) {
            gemm_nc<2>(aSH, aSL, obs, Bh + (size_t)nc * NC * Zn, nullptr, c, tid);
            const int r0 = wm * 16 + t4;
            const int s0 = ss[r0], s1 = ss[r0 + 8];
#pragma unroll
            for (int nt = 0; nt < 4; nt++) {
                const int col = wn * 32 + nt * 8 + t2;
                if (s0 >= 0) {
                    float2 o; o.x = c[nt][0]; o.y = c[nt][1];
                    *(float2*)(outv + (size_t)s0 * Un + nc * NC + col) = o;
                }
                if (s1 >= 0) {
                    float2 o; o.x = c[nt][2]; o.y = c[nt][3];
                    *(float2*)(outv + (size_t)s1 * Un + nc * NC + col) = o;
                }
            }
        }
    }
}

// ---------------- launcher ----------------
extern "C" void kernel_launch(void* const* d_in, const int* in_sizes, int n_in,
                              void* d_out, int out_size) {
    (void)in_sizes; (void)n_in; (void)out_size;
    const float* z   = (const float*)d_in[0];
    const float* u   = (const float*)d_in[1];
    const int*   rng = (const int*)d_in[2];
    const float* Wz  = (const float*)d_in[3];
    const float* bz  = (const float*)d_in[4];
    const float* Wh  = (const float*)d_in[5];
    const float* bh  = (const float*)d_in[6];
    const float* Wu  = (const float*)d_in[7];
    float* out = (float*)d_out;

    cudaFuncSetAttribute(k_moe, cudaFuncAttributeMaxDynamicSharedMemorySize, SMEM_DYN);

    k_zero<<<1, 32>>>();
    k_hist<<<Bn / 256, 256>>>(rng);
    k_scan<<<1, 32>>>();
    k_scatter<<<Bn / 256, 256>>>(rng);
    k_cvt_all<<<(NCVT + 255) / 256, 256>>>(z, u, Wz, Wh, Wu);
    k_moe<<<MAXT, NT, SMEM_DYN>>>(bz, bh, out);
}

// round 5
// speedup vs baseline: 5.2632x; 1.2762x over previous
#include <cuda_runtime.h>
#include <cuda_fp16.h>
#include <cstdint>

#define Bn 8192
#define En 16
#define Zn 256
#define Hn 1024
#define Un 256
#define TM 64
#define MAXT (Bn/TM + En)      // 144
#define NT 512
#define NC 128                 // N chunk
#define KC 64                  // K chunk
#define LDA 264                // A smem row stride (halves)
#define LDB 72                 // B smem row stride (halves)
#define BPART (128*LDB*2)      // 18432 B per buffer

// smem byte offsets
#define OASH 0
#define OASL (TM*LDA*2)
#define OA2H (2*TM*LDA*2)
#define OBS  (3*TM*LDA*2)            // 101376
#define SMEM_DYN (OBS + 3*BPART)     // 156672

// ---------------- device scratch ----------------
__device__ int g_perm[Bn];
__device__ int g_te[MAXT], g_ts[MAXT], g_tr[MAXT];
__device__ int g_ntiles;

__device__ __half g_Wzh[(size_t)En*Zn*Zn];
__device__ __half g_Whh[(size_t)En*Hn*Zn];
__device__ __half g_Wuh[(size_t)En*Un*Un];
__device__ __half g_zh[(size_t)Bn*Zn], g_zl[(size_t)Bn*Zn];
__device__ __half g_uh[(size_t)Bn*Un];

// ---------------- helpers ----------------
__device__ __forceinline__ uint32_t s2u(const void* p) {
    uint32_t a;
    asm("{ .reg .u64 t; cvta.to.shared.u64 t, %1; cvt.u32.u64 %0, t; }" : "=r"(a) : "l"(p));
    return a;
}
__device__ __forceinline__ void cpa16(uint32_t dst, const void* src, uint32_t sz) {
    asm volatile("cp.async.ca.shared.global [%0], [%1], 16, %2;"
                 :: "r"(dst), "l"(src), "r"(sz));
}
__device__ __forceinline__ void cpa_commit() { asm volatile("cp.async.commit_group;" ::: "memory"); }
template<int N> __device__ __forceinline__ void cpa_wait() {
    asm volatile("cp.async.wait_group %0;" :: "n"(N) : "memory");
}
__device__ __forceinline__ void ldm4(uint32_t r[4], uint32_t addr) {
    asm volatile("ldmatrix.sync.aligned.m8n8.x4.shared.b16 {%0,%1,%2,%3}, [%4];"
                 : "=r"(r[0]), "=r"(r[1]), "=r"(r[2]), "=r"(r[3]) : "r"(addr));
}
__device__ __forceinline__ void mma16816(float c[4], const uint32_t a[4], uint32_t b0, uint32_t b1) {
    asm volatile("mma.sync.aligned.m16n8k16.row.col.f32.f16.f16.f32 "
                 "{%0,%1,%2,%3}, {%4,%5,%6,%7}, {%8,%9}, {%0,%1,%2,%3};"
                 : "+f"(c[0]), "+f"(c[1]), "+f"(c[2]), "+f"(c[3])
                 : "r"(a[0]), "r"(a[1]), "r"(a[2]), "r"(a[3]), "r"(b0), "r"(b1));
}
__device__ __forceinline__ void hsplit(float x, __half& h, __half& l) {
    h = __float2half_rn(x);
    l = __float2half_rn(x - __half2float(h));
}

// ---------------- setup: hist + scan + tiles + scatter, one CTA ----------------
__global__ void k_setup(const int* __restrict__ rng) {
    __shared__ int sc[En];       // counts
    __shared__ int soff[En];     // offsets
    __shared__ int scur[En];     // scatter cursors
    const int tid = threadIdx.x;
    if (tid < En) { sc[tid] = 0; scur[tid] = 0; }
    __syncthreads();
    for (int i = tid; i < Bn; i += blockDim.x) atomicAdd(&sc[rng[i]], 1);
    __syncthreads();
    if (tid == 0) {
        int acc = 0, nt = 0;
        for (int e = 0; e < En; e++) {
            soff[e] = acc;
            int c = sc[e];
            for (int s = 0; s < c; s += TM) {
                g_te[nt] = e;
                g_ts[nt] = acc + s;
                g_tr[nt] = (c - s) < TM ? (c - s) : TM;
                nt++;
            }
            acc += c;
        }
        g_ntiles = nt;
    }
    __syncthreads();
    for (int i = tid; i < Bn; i += blockDim.x) {
        int e = rng[i];
        int p = atomicAdd(&scur[e], 1);
        g_perm[soff[e] + p] = i;
    }
}

// ---------------- fused fp32 -> fp16 converter ----------------
#define NWz (En*Zn*Zn/4)
#define NWh (En*Hn*Zn/4)
#define NWu (En*Un*Un/4)
#define Nz4 (Bn*Zn/4)
#define Nu4 (Bn*Un/4)
#define NCVT (NWz + NWh + NWu + Nz4 + Nu4)

__global__ void k_cvt_all(const float* __restrict__ z, const float* __restrict__ u,
                          const float* __restrict__ Wz, const float* __restrict__ Wh,
                          const float* __restrict__ Wu) {
    int i = blockIdx.x * blockDim.x + threadIdx.x;
    if (i >= NCVT) return;
    const float* src; __half* dh; __half* dl = nullptr; int j = i;
    if (j < NWz)                     { src = Wz; dh = g_Wzh; }
    else if ((j -= NWz) < NWh)       { src = Wh; dh = g_Whh; }
    else if ((j -= NWh) < NWu)       { src = Wu; dh = g_Wuh; }
    else if ((j -= NWu) < Nz4)       { src = z;  dh = g_zh; dl = g_zl; }
    else     { j -= Nz4;               src = u;  dh = g_uh; }
    float4 v = __ldg((const float4*)src + j);
    __half h0,h1,h2,h3,l0,l1,l2,l3;
    hsplit(v.x,h0,l0); hsplit(v.y,h1,l1); hsplit(v.z,h2,l2); hsplit(v.w,h3,l3);
    union { __half2 b[2]; uint2 q; } H, L;
    H.b[0] = __halves2half2(h0,h1); H.b[1] = __halves2half2(h2,h3);
    ((uint2*)dh)[j] = H.q;
    if (dl) {
        L.b[0] = __halves2half2(l0,l1); L.b[1] = __halves2half2(l2,l3);
        ((uint2*)dl)[j] = L.q;
    }
}

// ---------------- staging ----------------
// hi(+lo) A tile: 64 gathered rows x 256 halves
template<bool LO>
__device__ __forceinline__ void stage_a(uint32_t ah, uint32_t al,
                                        const __half* gh, const __half* gl,
                                        const int* ss, int tid) {
    for (int i = tid; i < TM * 32; i += NT) {
        int r = i >> 5, c = (i & 31) << 3;
        int s = ss[r];
        uint32_t sz = (s >= 0) ? 16u : 0u;
        size_t g = (size_t)(s >= 0 ? s : 0) * 256 + c;
        uint32_t o = (uint32_t)(r * LDA + c) * 2;
        cpa16(ah + o, gh + g, sz);
        if (LO) cpa16(al + o, gl + g, sz);
    }
}
// B chunk: 128 rows x 64 halves (hi only)
__device__ __forceinline__ void stage_b(uint32_t bh, const __half* gh, int kc, int tid) {
    for (int i = tid; i < 128 * 8; i += NT) {
        int r = i >> 3, c = (i & 7) << 3;
        size_t g = (size_t)r * 256 + kc * KC + c;
        cpa16(bh + (uint32_t)(r * LDB + c) * 2, gh + g, 16u);
    }
}

// ---------------- GEMM: one 64x128 output chunk ----------------
// PROD=2: c += Ah.Bh + Al.Bh   (GEMM1: A = z hi/lo, B = Wz hi)
// PROD=1: c += Ah.Bh           (GEMM2/3: plain fp16)
// Triple-buffered B, one barrier per K-chunk.
template<int PROD>
__device__ __forceinline__ void gemm_nc(uint32_t aH, uint32_t aL, uint32_t obs,
                                        const __half* gBh, float c[4][4], int tid) {
    const int lane = tid & 31, warp = tid >> 5;
    const int wm = warp >> 2, wn = warp & 3;
    const int lrow = (lane & 7) + ((lane >> 3) & 1) * 8;
    const int lk8  = (lane >> 4) * 8;

#pragma unroll
    for (int nt = 0; nt < 4; nt++)
#pragma unroll
        for (int j = 0; j < 4; j++) c[nt][j] = 0.f;

    stage_b(obs, gBh, 0, tid);
    cpa_commit();

    for (int kc = 0; kc < 4; kc++) {
        if (kc < 3) {
            stage_b(obs + (uint32_t)((kc + 1) % 3) * BPART, gBh, kc + 1, tid);
            cpa_commit();
            cpa_wait<1>();
        } else {
            cpa_wait<0>();
        }
        __syncthreads();

        const uint32_t bH = obs + (uint32_t)(kc % 3) * BPART;
#pragma unroll
        for (int k16 = 0; k16 < 4; k16++) {
            const int ka = kc * KC + k16 * 16;
            uint32_t ah[4], al[4];
            const uint32_t ao = (uint32_t)((wm * 16 + lrow) * LDA + ka + lk8) * 2;
            ldm4(ah, aH + ao);
            if (PROD == 2) ldm4(al, aL + ao);
            uint32_t bhf[2][4];
#pragma unroll
            for (int ng = 0; ng < 2; ng++) {
                const uint32_t bo = (uint32_t)((wn * 32 + ng * 16 + lrow) * LDB + k16 * 16 + lk8) * 2;
                ldm4(bhf[ng], bH + bo);
            }
#pragma unroll
            for (int nt = 0; nt < 4; nt++) {
                const int ng = nt >> 1, sel = nt & 1;
                mma16816(c[nt], ah, bhf[ng][sel], bhf[ng][sel + 2]);
                if (PROD == 2) mma16816(c[nt], al, bhf[ng][sel], bhf[ng][sel + 2]);
            }
        }
    }
}

// ---------------- fused MoE kernel ----------------
__global__ __launch_bounds__(NT, 1)
void k_moe(const float* __restrict__ bz, const float* __restrict__ bhb,
           float* __restrict__ out) {
    const int bt = blockIdx.x;
    if (bt >= g_ntiles) return;
    const int e = g_te[bt], start = g_ts[bt], rows = g_tr[bt];
    const int tid = threadIdx.x, lane = tid & 31, warp = tid >> 5;
    const int wm = warp >> 2, wn = warp & 3;
    const int t4 = lane >> 2, t2 = (lane & 3) * 2;

    extern __shared__ char smc[];
    const uint32_t sm0 = s2u(smc);
    const uint32_t aSH = sm0 + OASH, aSL = sm0 + OASL;
    const uint32_t a2H = sm0 + OA2H;
    const uint32_t obs = sm0 + OBS;

    __shared__ int ss[TM];
    if (tid < TM) ss[tid] = (tid < rows) ? g_perm[start + tid] : -1;
    __syncthreads();

    stage_a<true>(aSH, aSL, g_zh, g_zl, ss, tid);
    cpa_commit();

    float c[4][4];

    // ---- GEMM1: a = z @ Wz^T + bz -> A2H smem (fp16), 2-product ----
    {
        const __half* Bh = g_Wzh + (size_t)e * Zn * Zn;
        for (int nc = 0; nc < Zn / NC; nc++) {
            gemm_nc<2>(aSH, aSL, obs, Bh + (size_t)nc * NC * Zn, c, tid);
            const float* bzp = bz + (size_t)e * Zn + nc * NC;
            const int r0 = wm * 16 + t4;
#pragma unroll
            for (int nt = 0; nt < 4; nt++) {
                const int col = wn * 32 + nt * 8 + t2;
                const float2 bb = *(const float2*)(bzp + col);
                uint32_t o = (uint32_t)(r0 * LDA + nc * NC + col) * 2;
                *(__half2*)(smc + OA2H + o) = __floats2half2_rn(c[nt][0] + bb.x, c[nt][1] + bb.y);
                o = (uint32_t)((r0 + 8) * LDA + nc * NC + col) * 2;
                *(__half2*)(smc + OA2H + o) = __floats2half2_rn(c[nt][2] + bb.x, c[nt][3] + bb.y);
            }
        }
    }
    __syncthreads();

    // stage u (hi only) into aSH; GEMM1 done with z
    stage_a<false>(aSH, aSL, g_uh, nullptr, ss, tid);
    cpa_commit();

    // ---- GEMM2: h = relu(a @ Wh^T + bh) -> out, 1-product ----
    {
        const __half* Bh = g_Whh + (size_t)e * Hn * Zn;
        for (int nc = 0; nc < Hn / NC; nc++) {
            gemm_nc<1>(a2H, a2H, obs, Bh + (size_t)nc * NC * Zn, c, tid);
            const float* bhp = bhb + (size_t)e * Hn + nc * NC;
            const int r0 = wm * 16 + t4;
            const int s0 = ss[r0], s1 = ss[r0 + 8];
#pragma unroll
            for (int nt = 0; nt < 4; nt++) {
                const int col = wn * 32 + nt * 8 + t2;
                const float2 bb = *(const float2*)(bhp + col);
                if (s0 >= 0) {
                    float2 o;
                    o.x = fmaxf(c[nt][0] + bb.x, 0.f);
                    o.y = fmaxf(c[nt][1] + bb.y, 0.f);
                    *(float2*)(out + (size_t)s0 * Hn + nc * NC + col) = o;
                }
                if (s1 >= 0) {
                    float2 o;
                    o.x = fmaxf(c[nt][2] + bb.x, 0.f);
                    o.y = fmaxf(c[nt][3] + bb.y, 0.f);
                    *(float2*)(out + (size_t)s1 * Hn + nc * NC + col) = o;
                }
            }
        }
    }

    // ---- GEMM3: v = u @ Wu^T -> out + Bn*Hn, 1-product ----
    {
        const __half* Bh = g_Wuh + (size_t)e * Un * Un;
        float* outv = out + (size_t)Bn * Hn;
        for (int nc = 0; nc < Un / NC; nc++) {
            gemm_nc<1>(aSH, aSH, obs, Bh + (size_t)nc * NC * Zn, c, tid);
            const int r0 = wm * 16 + t4;
            const int s0 = ss[r0], s1 = ss[r0 + 8];
#pragma unroll
            for (int nt = 0; nt < 4; nt++) {
                const int col = wn * 32 + nt * 8 + t2;
                if (s0 >= 0) {
                    float2 o; o.x = c[nt][0]; o.y = c[nt][1];
                    *(float2*)(outv + (size_t)s0 * Un + nc * NC + col) = o;
                }
                if (s1 >= 0) {
                    float2 o; o.x = c[nt][2]; o.y = c[nt][3];
                    *(float2*)(outv + (size_t)s1 * Un + nc * NC + col) = o;
                }
            }
        }
    }
}

// ---------------- launcher ----------------
extern "C" void kernel_launch(void* const* d_in, const int* in_sizes, int n_in,
                              void* d_out, int out_size) {
    (void)in_sizes; (void)n_in; (void)out_size;
    const float* z   = (const float*)d_in[0];
    const float* u   = (const float*)d_in[1];
    const int*   rng = (const int*)d_in[2];
    const float* Wz  = (const float*)d_in[3];
    const float* bz  = (const float*)d_in[4];
    const float* Wh  = (const float*)d_in[5];
    const float* bh  = (const float*)d_in[6];
    const float* Wu  = (const float*)d_in[7];
    float* out = (float*)d_out;

    cudaFuncSetAttribute(k_moe, cudaFuncAttributeMaxDynamicSharedMemorySize, SMEM_DYN);

    k_setup<<<1, 1024>>>(rng);
    k_cvt_all<<<(NCVT + 255) / 256, 256>>>(z, u, Wz, Wh, Wu);
    k_moe<<<MAXT, NT, SMEM_DYN>>>(bz, bh, out);
}